// round 2
// baseline (speedup 1.0000x reference)
#include <cuda_runtime.h>
#include <math.h>

#define BATCH 64
#define IC 32
#define OC 32
#define NM 64
#define HW 4096
#define CTRLD 512
#define ROWS 4160        // NF(64) + NI(2048) + NO(2048)
#define KSPLIT 4
#define OUT_ELEMS (BATCH * OC * HW)

// scratch for control-GEMM partials: [ksplit][batch][row]
__device__ float g_ctrl[KSPLIT * BATCH * ROWS];

typedef unsigned long long ull;

__device__ __forceinline__ ull fma2(ull a, ull b, ull c) {
    ull d;
    asm("fma.rn.f32x2 %0, %1, %2, %3;" : "=l"(d) : "l"(a), "l"(b), "l"(c));
    return d;
}
__device__ __forceinline__ ull pack2(float lo, float hi) {
    ull d;
    asm("mov.b64 %0, {%1, %2};" : "=l"(d) : "f"(lo), "f"(hi));
    return d;
}
__device__ __forceinline__ void unpack2(ull v, float& lo, float& hi) {
    asm("mov.b64 {%0, %1}, %2;" : "=f"(lo), "=f"(hi) : "l"(v));
}
__device__ __forceinline__ float tanh_fast(float x) {
    float y;
    asm("tanh.approx.f32 %0, %1;" : "=f"(y) : "f"(x));
    return y;
}

// ---------------------------------------------------------------------------
// Kernel 1: ctrl = controls @ W.T, K split 4 ways (grid 65 x 4).
// ---------------------------------------------------------------------------
__global__ __launch_bounds__(256) void ctrl_gemm(
    const float* __restrict__ controls,   // [64, 512]
    const float* __restrict__ W)          // [4160, 512]
{
    __shared__ float sW[32 * 68];   // [k][r]
    __shared__ float sC[32 * 68];   // [k][b]

    const int r0    = blockIdx.x * 64;
    const int kz    = blockIdx.y;
    const int kbase = kz * (CTRLD / KSPLIT);
    const int tid   = threadIdx.x;
    const int ty    = tid >> 4;
    const int tx    = tid & 15;

    float acc[4][4] = {};

    for (int kc0 = 0; kc0 < CTRLD / KSPLIT; kc0 += 32) {
        #pragma unroll
        for (int i = tid; i < 64 * 32; i += 256) {
            int r = i >> 5, k = i & 31;
            sW[k * 68 + r] = W[(size_t)(r0 + r) * CTRLD + kbase + kc0 + k];
        }
        #pragma unroll
        for (int i = tid; i < 64 * 32; i += 256) {
            int b = i >> 5, k = i & 31;
            sC[k * 68 + b] = controls[b * CTRLD + kbase + kc0 + k];
        }
        __syncthreads();

        #pragma unroll
        for (int k = 0; k < 32; k++) {
            float4 a  = *(const float4*)&sW[k * 68 + ty * 4];
            float4 bb = *(const float4*)&sC[k * 68 + tx * 4];
            float av[4] = {a.x, a.y, a.z, a.w};
            float bv[4] = {bb.x, bb.y, bb.z, bb.w};
            #pragma unroll
            for (int i = 0; i < 4; i++)
                #pragma unroll
                for (int j = 0; j < 4; j++)
                    acc[i][j] = fmaf(av[i], bv[j], acc[i][j]);
        }
        __syncthreads();
    }

    #pragma unroll
    for (int i = 0; i < 4; i++) {
        int r = r0 + ty * 4 + i;
        #pragma unroll
        for (int j = 0; j < 4; j++) {
            int b = tx * 4 + j;
            g_ctrl[kz * (BATCH * ROWS) + b * ROWS + r] = acc[i][j];
        }
    }
}

// ---------------------------------------------------------------------------
// Kernel 2: fused gated-input GEMM + state update + tanh + output GEMM.
// f32x2 packed math; gates staged pre-duplicated for broadcast FMA2.
// grid (HW/128, BATCH), 256 threads, 128 pixels per block.
// ---------------------------------------------------------------------------
__global__ __launch_bounds__(256, 2) void vstm_main(
    const float* __restrict__ inputs,     // [B, 32, 4096]
    const float* __restrict__ state,      // [B, 64, 4096]
    float* __restrict__ outputs,          // [B, 32, 4096]
    float* __restrict__ new_state)        // [B, 64, 4096]
{
    extern __shared__ float sm[];
    float*  s_in    = sm;                       // [32][128]            4096 f
    float*  s_t     = s_in + 32 * 128;          // [64][128]            8192 f
    float2* s_gin2  = (float2*)(s_t + 64 * 128);     // [c][66] f2      4224 f
    float2* s_gout2 = s_gin2 + 32 * 66;              // [m][34] f2      4352 f
    float*  s_f     = (float*)(s_gout2 + 64 * 34);   // [64]

    const int b   = blockIdx.y;
    const int p0  = blockIdx.x * 128;
    const int tid = threadIdx.x;

    // ---- stage gates (sum the 4 K-split partials, duplicate each value) ----
    {
        const float* gc = g_ctrl + b * ROWS;
        for (int i = tid; i < ROWS; i += 256) {
            float v = gc[i] + gc[BATCH * ROWS + i]
                    + gc[2 * BATCH * ROWS + i] + gc[3 * BATCH * ROWS + i];
            if (i < 64) {
                s_f[i] = v;
            } else if (i < 64 + 2048) {
                int j = i - 64;                         // in_gates [m][c]
                s_gin2[(j & 31) * 66 + (j >> 5)] = make_float2(v, v);   // -> [c][m]
            } else {
                int j = i - 2112;                       // out_gates [o][m]
                s_gout2[(j & 63) * 34 + (j >> 6)] = make_float2(v, v);  // -> [m][o]
            }
        }
    }

    // ---- stage input tile [32][128] ----
    const float* inb = inputs + (size_t)b * (IC * HW) + p0;
    #pragma unroll
    for (int i = tid; i < 32 * 32; i += 256) {
        int c = i >> 5, p4 = i & 31;
        *(float4*)&s_in[c * 128 + p4 * 4] = *(const float4*)&inb[c * 4096 + p4 * 4];
    }
    __syncthreads();

    const int tx = tid & 31;     // 4 pixels = 2 f32x2 pairs
    const int ty = tid >> 5;     // 0..7
    const int pp = tx * 4;

    // ---- phase 1: gated = gin(64x32) @ in(32x128); thread = 8m x 4p ----
    {
        const int m0 = ty * 8;
        ull acc[8][2] = {};
        #pragma unroll
        for (int c = 0; c < 32; c++) {
            const ulonglong2* ga = (const ulonglong2*)&s_gin2[c * 66 + m0];
            ulonglong2 a01 = ga[0], a23 = ga[1], a45 = ga[2], a67 = ga[3];
            ulonglong2 bv  = *(const ulonglong2*)&s_in[c * 128 + pp];
            ull av[8] = {a01.x, a01.y, a23.x, a23.y, a45.x, a45.y, a67.x, a67.y};
            #pragma unroll
            for (int i = 0; i < 8; i++) {
                acc[i][0] = fma2(av[i], bv.x, acc[i][0]);
                acc[i][1] = fma2(av[i], bv.y, acc[i][1]);
            }
        }

        const float* stb = state + (size_t)b * (NM * HW) + p0 + pp;
        float*       nsb = new_state + (size_t)b * (NM * HW) + p0 + pp;
        #pragma unroll
        for (int i = 0; i < 8; i++) {
            int m = m0 + i;
            float f = s_f[m];
            ull f2 = pack2(f, f);
            ulonglong2 st = *(const ulonglong2*)&stb[(size_t)m * 4096];
            ull ns0 = fma2(st.x, f2, acc[i][0]);
            ull ns1 = fma2(st.y, f2, acc[i][1]);
            ulonglong2 nsv; nsv.x = ns0; nsv.y = ns1;
            *(ulonglong2*)&nsb[(size_t)m * 4096] = nsv;
            float x0, x1, x2, x3;
            unpack2(ns0, x0, x1);
            unpack2(ns1, x2, x3);
            ulonglong2 tv;
            tv.x = pack2(tanh_fast(x0), tanh_fast(x1));
            tv.y = pack2(tanh_fast(x2), tanh_fast(x3));
            *(ulonglong2*)&s_t[m * 128 + pp] = tv;
        }
    }
    __syncthreads();

    // ---- phase 2: out = gout(32x64) @ t(64x128); thread = 4o x 4p ----
    {
        const int o0 = ty * 4;
        ull acc[4][2] = {};
        #pragma unroll
        for (int m = 0; m < 64; m++) {
            const ulonglong2* ga = (const ulonglong2*)&s_gout2[m * 34 + o0];
            ulonglong2 a01 = ga[0], a23 = ga[1];
            ulonglong2 bv  = *(const ulonglong2*)&s_t[m * 128 + pp];
            ull av[4] = {a01.x, a01.y, a23.x, a23.y};
            #pragma unroll
            for (int i = 0; i < 4; i++) {
                acc[i][0] = fma2(av[i], bv.x, acc[i][0]);
                acc[i][1] = fma2(av[i], bv.y, acc[i][1]);
            }
        }

        float* ob = outputs + (size_t)b * (OC * HW) + p0 + pp;
        #pragma unroll
        for (int i = 0; i < 4; i++) {
            ulonglong2 v; v.x = acc[i][0]; v.y = acc[i][1];
            *(ulonglong2*)&ob[(size_t)(o0 + i) * 4096] = v;
        }
    }
}

// ---------------------------------------------------------------------------
extern "C" void kernel_launch(void* const* d_in, const int* in_sizes, int n_in,
                              void* d_out, int out_size) {
    const float* inputs   = (const float*)d_in[0];   // [64,32,64,64]
    const float* state    = (const float*)d_in[1];   // [64,64,64,64]
    const float* controls = (const float*)d_in[2];   // [64,512]
    const float* W        = (const float*)d_in[3];   // [4160,512]

    float* outputs   = (float*)d_out;
    float* new_state = outputs + OUT_ELEMS;

    ctrl_gemm<<<dim3(65, KSPLIT), 256>>>(controls, W);

    const size_t smem = (32 * 128 + 64 * 128 + 32 * 66 * 2 + 64 * 34 * 2 + 64) * sizeof(float);
    cudaFuncSetAttribute(vstm_main, cudaFuncAttributeMaxDynamicSharedMemorySize, (int)smem);
    vstm_main<<<dim3(HW / 128, BATCH), 256, smem>>>(inputs, state, outputs, new_state);
}

// round 3
// speedup vs baseline: 1.2425x; 1.2425x over previous
#include <cuda_runtime.h>
#include <math.h>

#define BATCH 64
#define IC 32
#define OC 32
#define NM 64
#define HW 4096
#define CTRLD 512
#define ROWS 4160        // NF(64) + NI(2048) + NO(2048)
#define KSPLIT 8
#define OUT_ELEMS (BATCH * OC * HW)

// scratch: K-split partials [ksplit][batch][row], then reduced gates [batch][row]
__device__ float g_ctrl[KSPLIT * BATCH * ROWS];
__device__ float g_gates[BATCH * ROWS];

__device__ __forceinline__ float tanh_fast(float x) {
    float y;
    asm("tanh.approx.f32 %0, %1;" : "=f"(y) : "f"(x));
    return y;
}

// ---------------------------------------------------------------------------
// Kernel 1: ctrl partials = controls @ W.T, K split 8 ways (grid 65 x 8).
// ---------------------------------------------------------------------------
__global__ __launch_bounds__(256) void ctrl_gemm(
    const float* __restrict__ controls,   // [64, 512]
    const float* __restrict__ W)          // [4160, 512]
{
    __shared__ float sW[32 * 68];   // [k][r]
    __shared__ float sC[32 * 68];   // [k][b]

    const int r0    = blockIdx.x * 64;
    const int kz    = blockIdx.y;
    const int kbase = kz * (CTRLD / KSPLIT);   // 64 per split
    const int tid   = threadIdx.x;
    const int ty    = tid >> 4;
    const int tx    = tid & 15;

    float acc[4][4] = {};

    #pragma unroll
    for (int kc0 = 0; kc0 < CTRLD / KSPLIT; kc0 += 32) {
        #pragma unroll
        for (int i = tid; i < 64 * 32; i += 256) {
            int r = i >> 5, k = i & 31;
            sW[k * 68 + r] = W[(size_t)(r0 + r) * CTRLD + kbase + kc0 + k];
        }
        #pragma unroll
        for (int i = tid; i < 64 * 32; i += 256) {
            int b = i >> 5, k = i & 31;
            sC[k * 68 + b] = controls[b * CTRLD + kbase + kc0 + k];
        }
        __syncthreads();

        #pragma unroll
        for (int k = 0; k < 32; k++) {
            float4 a  = *(const float4*)&sW[k * 68 + ty * 4];
            float4 bb = *(const float4*)&sC[k * 68 + tx * 4];
            float av[4] = {a.x, a.y, a.z, a.w};
            float bv[4] = {bb.x, bb.y, bb.z, bb.w};
            #pragma unroll
            for (int i = 0; i < 4; i++)
                #pragma unroll
                for (int j = 0; j < 4; j++)
                    acc[i][j] = fmaf(av[i], bv[j], acc[i][j]);
        }
        __syncthreads();
    }

    #pragma unroll
    for (int i = 0; i < 4; i++) {
        int r = r0 + ty * 4 + i;
        #pragma unroll
        for (int j = 0; j < 4; j++) {
            int b = tx * 4 + j;
            g_ctrl[kz * (BATCH * ROWS) + b * ROWS + r] = acc[i][j];
        }
    }
}

// ---------------------------------------------------------------------------
// Kernel 1b: reduce the 8 partials -> g_gates. 520 x 512 = 266240 = BATCH*ROWS.
// ---------------------------------------------------------------------------
__global__ __launch_bounds__(512) void ctrl_reduce()
{
    int i = blockIdx.x * 512 + threadIdx.x;
    float v = 0.f;
    #pragma unroll
    for (int k = 0; k < KSPLIT; k++)
        v += g_ctrl[k * (BATCH * ROWS) + i];
    g_gates[i] = v;
}

// ---------------------------------------------------------------------------
// Kernel 2: fused gated-input GEMM + state update + tanh + output GEMM.
// 512 threads, 128 pixels/block, grid (32, 64).
// Phase1 thread tile 4m x 4p; Phase2 thread tile 4o x 2p.
// ---------------------------------------------------------------------------
__global__ __launch_bounds__(512, 2) void vstm_main(
    const float* __restrict__ inputs,     // [B, 32, 4096]
    const float* __restrict__ state,      // [B, 64, 4096]
    float* __restrict__ outputs,          // [B, 32, 4096]
    float* __restrict__ new_state)        // [B, 64, 4096]
{
    extern __shared__ float sm[];
    float* s_in   = sm;                     // [32][128]    4096
    float* s_t    = s_in + 32 * 128;        // [64][128]    8192
    float* s_gin  = s_t + 64 * 128;         // [c][68]      2176  (-> [c][m])
    float* s_gout = s_gin + 32 * 68;        // [m][36]      2304  (-> [m][o])
    float* s_f    = s_gout + 64 * 36;       // [64]

    const int b   = blockIdx.y;
    const int p0  = blockIdx.x * 128;
    const int tid = threadIdx.x;

    // ---- stage gates from reduced g_gates ----
    {
        const float* gc = g_gates + b * ROWS;
        for (int i = tid; i < ROWS; i += 512) {
            float v = gc[i];
            if (i < 64) {
                s_f[i] = v;
            } else if (i < 64 + 2048) {
                int j = i - 64;                         // in_gates [m][c]
                s_gin[(j & 31) * 68 + (j >> 5)] = v;    // -> [c][m]
            } else {
                int j = i - 2112;                       // out_gates [o][m]
                s_gout[(j & 63) * 36 + (j >> 6)] = v;   // -> [m][o]
            }
        }
    }

    // ---- stage input tile [32][128] ----
    const float* inb = inputs + (size_t)b * (IC * HW) + p0;
    #pragma unroll
    for (int i = tid; i < 32 * 32; i += 512) {
        int c = i >> 5, p4 = i & 31;
        *(float4*)&s_in[c * 128 + p4 * 4] = *(const float4*)&inb[c * 4096 + p4 * 4];
    }
    __syncthreads();

    const int lane = tid & 31;
    const int wid  = tid >> 5;      // 0..15

    // ---- phase 1: gated = gin(64x32) @ in(32x128); thread = 4m x 4p ----
    {
        const int m0 = wid * 4;     // 16 warps cover 64 m
        const int pp = lane * 4;    // 32 lanes cover 128 p
        float acc[4][4] = {};
        #pragma unroll
        for (int c = 0; c < 32; c++) {
            float4 a  = *(const float4*)&s_gin[c * 68 + m0];   // broadcast in warp
            float4 bb = *(const float4*)&s_in[c * 128 + pp];
            float av[4] = {a.x, a.y, a.z, a.w};
            float bv[4] = {bb.x, bb.y, bb.z, bb.w};
            #pragma unroll
            for (int i = 0; i < 4; i++)
                #pragma unroll
                for (int j = 0; j < 4; j++)
                    acc[i][j] = fmaf(av[i], bv[j], acc[i][j]);
        }

        const float* stb = state + (size_t)b * (NM * HW) + p0 + pp;
        float*       nsb = new_state + (size_t)b * (NM * HW) + p0 + pp;
        #pragma unroll
        for (int i = 0; i < 4; i++) {
            int m = m0 + i;
            float f = s_f[m];
            float4 st = *(const float4*)&stb[(size_t)m * 4096];
            float4 ns;
            ns.x = fmaf(st.x, f, acc[i][0]);
            ns.y = fmaf(st.y, f, acc[i][1]);
            ns.z = fmaf(st.z, f, acc[i][2]);
            ns.w = fmaf(st.w, f, acc[i][3]);
            *(float4*)&nsb[(size_t)m * 4096] = ns;
            float4 t;
            t.x = tanh_fast(ns.x);
            t.y = tanh_fast(ns.y);
            t.z = tanh_fast(ns.z);
            t.w = tanh_fast(ns.w);
            *(float4*)&s_t[m * 128 + pp] = t;
        }
    }
    __syncthreads();

    // ---- phase 2: out = gout(32x64) @ t(64x128); thread = 4o x 2p ----
    {
        const int o0 = (wid & 7) * 4;            // warps 0-7 / 8-15 split pixels
        const int pp = lane * 2 + (wid >> 3) * 64;
        float acc[4][2] = {};
        #pragma unroll
        for (int m = 0; m < 64; m++) {
            float4 a  = *(const float4*)&s_gout[m * 36 + o0];  // broadcast in warp
            float2 bb = *(const float2*)&s_t[m * 128 + pp];
            float av[4] = {a.x, a.y, a.z, a.w};
            #pragma unroll
            for (int i = 0; i < 4; i++) {
                acc[i][0] = fmaf(av[i], bb.x, acc[i][0]);
                acc[i][1] = fmaf(av[i], bb.y, acc[i][1]);
            }
        }

        float* ob = outputs + (size_t)b * (OC * HW) + p0 + pp;
        #pragma unroll
        for (int i = 0; i < 4; i++) {
            float2 v = make_float2(acc[i][0], acc[i][1]);
            *(float2*)&ob[(size_t)(o0 + i) * 4096] = v;
        }
    }
}

// ---------------------------------------------------------------------------
extern "C" void kernel_launch(void* const* d_in, const int* in_sizes, int n_in,
                              void* d_out, int out_size) {
    const float* inputs   = (const float*)d_in[0];   // [64,32,64,64]
    const float* state    = (const float*)d_in[1];   // [64,64,64,64]
    const float* controls = (const float*)d_in[2];   // [64,512]
    const float* W        = (const float*)d_in[3];   // [4160,512]

    float* outputs   = (float*)d_out;
    float* new_state = outputs + OUT_ELEMS;

    ctrl_gemm<<<dim3(65, KSPLIT), 256>>>(controls, W);
    ctrl_reduce<<<(BATCH * ROWS) / 512, 512>>>();

    const size_t smem = (32 * 128 + 64 * 128 + 32 * 68 + 64 * 36 + 64) * sizeof(float);
    cudaFuncSetAttribute(vstm_main, cudaFuncAttributeMaxDynamicSharedMemorySize, (int)smem);
    vstm_main<<<dim3(HW / 128, BATCH), 512, smem>>>(inputs, state, outputs, new_state);
}

// round 4
// speedup vs baseline: 1.2666x; 1.0194x over previous
#include <cuda_runtime.h>
#include <math.h>

#define BATCH 64
#define IC 32
#define OC 32
#define NM 64
#define HW 4096
#define CTRLD 512
#define ROWS 4160        // NF(64) + NI(2048) + NO(2048)
#define KSPLIT 4
#define OUT_ELEMS (BATCH * OC * HW)

// scratch: K-split partials [ksplit][batch][row], then reduced gates [batch][row]
__device__ float g_ctrl[KSPLIT * BATCH * ROWS];
__device__ float g_gates[BATCH * ROWS];

__device__ __forceinline__ float tanh_fast(float x) {
    float y;
    asm("tanh.approx.f32 %0, %1;" : "=f"(y) : "f"(x));
    return y;
}

// ---------------------------------------------------------------------------
// Kernel 1: ctrl partials = controls @ W.T, K split 4 ways (grid 65 x 4).
// Double-buffered K-chunks of 16; float4 staging loads.
// ---------------------------------------------------------------------------
__global__ __launch_bounds__(256) void ctrl_gemm(
    const float* __restrict__ controls,   // [64, 512]
    const float* __restrict__ W)          // [4160, 512]
{
    __shared__ float sW[2][16 * 68];   // [k][r], padded 68
    __shared__ float sC[2][16 * 68];   // [k][b], padded 68

    const int r0    = blockIdx.x * 64;
    const int kz    = blockIdx.y;
    const int kbase = kz * (CTRLD / KSPLIT);   // 128 per split
    const int tid   = threadIdx.x;
    const int ty    = tid >> 4;     // 0..15
    const int tx    = tid & 15;     // 0..15

    // staging coords: each thread loads one float4 of W and one of controls
    const int sr = tid >> 2;          // 0..63 (row / batch)
    const int sk = (tid & 3) * 4;     // 0,4,8,12 (k offset within chunk)

    const float* wp = W + (size_t)(r0 + sr) * CTRLD + kbase + sk;
    const float* cp = controls + sr * CTRLD + kbase + sk;

    float acc[4][4] = {};

    // prologue: stage chunk 0 into buffer 0
    {
        float4 wv = *(const float4*)wp;
        float4 cv = *(const float4*)cp;
        sW[0][(sk + 0) * 68 + sr] = wv.x;
        sW[0][(sk + 1) * 68 + sr] = wv.y;
        sW[0][(sk + 2) * 68 + sr] = wv.z;
        sW[0][(sk + 3) * 68 + sr] = wv.w;
        sC[0][(sk + 0) * 68 + sr] = cv.x;
        sC[0][(sk + 1) * 68 + sr] = cv.y;
        sC[0][(sk + 2) * 68 + sr] = cv.z;
        sC[0][(sk + 3) * 68 + sr] = cv.w;
    }
    __syncthreads();

    #pragma unroll
    for (int c = 0; c < 8; c++) {
        const int cur = c & 1;
        const int nxt = cur ^ 1;

        // issue next chunk's loads first (hide latency behind compute)
        float4 wv, cv;
        if (c < 7) {
            wv = *(const float4*)(wp + (c + 1) * 16);
            cv = *(const float4*)(cp + (c + 1) * 16);
        }

        #pragma unroll
        for (int k = 0; k < 16; k++) {
            float4 a  = *(const float4*)&sW[cur][k * 68 + ty * 4];
            float4 bb = *(const float4*)&sC[cur][k * 68 + tx * 4];
            float av[4] = {a.x, a.y, a.z, a.w};
            float bv[4] = {bb.x, bb.y, bb.z, bb.w};
            #pragma unroll
            for (int i = 0; i < 4; i++)
                #pragma unroll
                for (int j = 0; j < 4; j++)
                    acc[i][j] = fmaf(av[i], bv[j], acc[i][j]);
        }

        if (c < 7) {
            sW[nxt][(sk + 0) * 68 + sr] = wv.x;
            sW[nxt][(sk + 1) * 68 + sr] = wv.y;
            sW[nxt][(sk + 2) * 68 + sr] = wv.z;
            sW[nxt][(sk + 3) * 68 + sr] = wv.w;
            sC[nxt][(sk + 0) * 68 + sr] = cv.x;
            sC[nxt][(sk + 1) * 68 + sr] = cv.y;
            sC[nxt][(sk + 2) * 68 + sr] = cv.z;
            sC[nxt][(sk + 3) * 68 + sr] = cv.w;
            __syncthreads();
        }
    }

    #pragma unroll
    for (int i = 0; i < 4; i++) {
        int r = r0 + ty * 4 + i;
        #pragma unroll
        for (int j = 0; j < 4; j++) {
            int b = tx * 4 + j;
            g_ctrl[kz * (BATCH * ROWS) + b * ROWS + r] = acc[i][j];
        }
    }
}

// ---------------------------------------------------------------------------
// Kernel 1b: reduce the 4 partials -> g_gates. 520 x 512 threads.
// ---------------------------------------------------------------------------
__global__ __launch_bounds__(512) void ctrl_reduce()
{
    int i = blockIdx.x * 512 + threadIdx.x;
    float v = 0.f;
    #pragma unroll
    for (int k = 0; k < KSPLIT; k++)
        v += g_ctrl[k * (BATCH * ROWS) + i];
    g_gates[i] = v;
}

// ---------------------------------------------------------------------------
// Kernel 2: fused gated-input GEMM + state update + tanh + output GEMM.
// 512 threads, 128 pixels/block, grid (32, 64).
// ---------------------------------------------------------------------------
__global__ __launch_bounds__(512, 2) void vstm_main(
    const float* __restrict__ inputs,     // [B, 32, 4096]
    const float* __restrict__ state,      // [B, 64, 4096]
    float* __restrict__ outputs,          // [B, 32, 4096]
    float* __restrict__ new_state)        // [B, 64, 4096]
{
    extern __shared__ float sm[];
    float* s_in   = sm;                     // [32][128]    4096
    float* s_t    = s_in + 32 * 128;        // [64][128]    8192
    float* s_gin  = s_t + 64 * 128;         // [c][68]      2176  (-> [c][m])
    float* s_gout = s_gin + 32 * 68;        // [m][36]      2304  (-> [m][o])
    float* s_f    = s_gout + 64 * 36;       // [64]

    const int b   = blockIdx.y;
    const int p0  = blockIdx.x * 128;
    const int tid = threadIdx.x;

    // ---- stage gates from reduced g_gates ----
    {
        const float* gc = g_gates + b * ROWS;
        for (int i = tid; i < ROWS; i += 512) {
            float v = gc[i];
            if (i < 64) {
                s_f[i] = v;
            } else if (i < 64 + 2048) {
                int j = i - 64;                         // in_gates [m][c]
                s_gin[(j & 31) * 68 + (j >> 5)] = v;    // -> [c][m]
            } else {
                int j = i - 2112;                       // out_gates [o][m]
                s_gout[(j & 63) * 36 + (j >> 6)] = v;   // -> [m][o]
            }
        }
    }

    // ---- stage input tile [32][128] ----
    const float* inb = inputs + (size_t)b * (IC * HW) + p0;
    #pragma unroll
    for (int i = tid; i < 32 * 32; i += 512) {
        int c = i >> 5, p4 = i & 31;
        *(float4*)&s_in[c * 128 + p4 * 4] = *(const float4*)&inb[c * 4096 + p4 * 4];
    }
    __syncthreads();

    const int lane = tid & 31;
    const int wid  = tid >> 5;      // 0..15

    // ---- phase 1: gated = gin(64x32) @ in(32x128); thread = 4m x 4p ----
    {
        const int m0 = wid * 4;
        const int pp = lane * 4;
        float acc[4][4] = {};
        #pragma unroll
        for (int c = 0; c < 32; c++) {
            float4 a  = *(const float4*)&s_gin[c * 68 + m0];
            float4 bb = *(const float4*)&s_in[c * 128 + pp];
            float av[4] = {a.x, a.y, a.z, a.w};
            float bv[4] = {bb.x, bb.y, bb.z, bb.w};
            #pragma unroll
            for (int i = 0; i < 4; i++)
                #pragma unroll
                for (int j = 0; j < 4; j++)
                    acc[i][j] = fmaf(av[i], bv[j], acc[i][j]);
        }

        const float* stb = state + (size_t)b * (NM * HW) + p0 + pp;
        float*       nsb = new_state + (size_t)b * (NM * HW) + p0 + pp;
        #pragma unroll
        for (int i = 0; i < 4; i++) {
            int m = m0 + i;
            float f = s_f[m];
            float4 st = *(const float4*)&stb[(size_t)m * 4096];
            float4 ns;
            ns.x = fmaf(st.x, f, acc[i][0]);
            ns.y = fmaf(st.y, f, acc[i][1]);
            ns.z = fmaf(st.z, f, acc[i][2]);
            ns.w = fmaf(st.w, f, acc[i][3]);
            *(float4*)&nsb[(size_t)m * 4096] = ns;
            float4 t;
            t.x = tanh_fast(ns.x);
            t.y = tanh_fast(ns.y);
            t.z = tanh_fast(ns.z);
            t.w = tanh_fast(ns.w);
            *(float4*)&s_t[m * 128 + pp] = t;
        }
    }
    __syncthreads();

    // ---- phase 2: out = gout(32x64) @ t(64x128); thread = 4o x 2p ----
    {
        const int o0 = (wid & 7) * 4;
        const int pp = lane * 2 + (wid >> 3) * 64;
        float acc[4][2] = {};
        #pragma unroll
        for (int m = 0; m < 64; m++) {
            float4 a  = *(const float4*)&s_gout[m * 36 + o0];
            float2 bb = *(const float2*)&s_t[m * 128 + pp];
            float av[4] = {a.x, a.y, a.z, a.w};
            #pragma unroll
            for (int i = 0; i < 4; i++) {
                acc[i][0] = fmaf(av[i], bb.x, acc[i][0]);
                acc[i][1] = fmaf(av[i], bb.y, acc[i][1]);
            }
        }

        float* ob = outputs + (size_t)b * (OC * HW) + p0 + pp;
        #pragma unroll
        for (int i = 0; i < 4; i++) {
            float2 v = make_float2(acc[i][0], acc[i][1]);
            *(float2*)&ob[(size_t)(o0 + i) * 4096] = v;
        }
    }
}

// ---------------------------------------------------------------------------
extern "C" void kernel_launch(void* const* d_in, const int* in_sizes, int n_in,
                              void* d_out, int out_size) {
    const float* inputs   = (const float*)d_in[0];   // [64,32,64,64]
    const float* state    = (const float*)d_in[1];   // [64,64,64,64]
    const float* controls = (const float*)d_in[2];   // [64,512]
    const float* W        = (const float*)d_in[3];   // [4160,512]

    float* outputs   = (float*)d_out;
    float* new_state = outputs + OUT_ELEMS;

    ctrl_gemm<<<dim3(65, KSPLIT), 256>>>(controls, W);
    ctrl_reduce<<<(BATCH * ROWS) / 512, 512>>>();

    const size_t smem = (32 * 128 + 64 * 128 + 32 * 68 + 64 * 36 + 64) * sizeof(float);
    cudaFuncSetAttribute(vstm_main, cudaFuncAttributeMaxDynamicSharedMemorySize, (int)smem);
    vstm_main<<<dim3(HW / 128, BATCH), 512, smem>>>(inputs, state, outputs, new_state);
}